// round 5
// baseline (speedup 1.0000x reference)
#include <cuda_runtime.h>

// Problem constants (shapes fixed for this instance)
#define NNODES 8192
#define CCH    256
// bitmap over NNODES*NNODES = 2^26 keys -> 2^21 uint32 words = 8 MiB
#define BM_WORDS (1u << 21)

__device__ __align__(16) unsigned g_bitmap[BM_WORDS];
__device__ float                  g_partial[64 * CCH];
__device__ unsigned long long     g_nnz;
__device__ int                    g_stride;   // 1 = int32 ids, 2 = int64 ids (low word)

// ---------------------------------------------------------------------------
// K0: dtype probe. If edge_index is int64, every odd 32-bit word of the
// first 8192 pairs is 0 (ids < 8192, little-endian). For int32 data that
// pattern is impossible in practice. One block, ballot-reduce.
// ---------------------------------------------------------------------------
__global__ void k_detect(const int* __restrict__ w, int nwords) {
    __shared__ int any_nonzero;
    if (threadIdx.x == 0) any_nonzero = 0;
    __syncthreads();
    // scan odd words in [1, 16384) (well within 2 MiB minimum buffer)
    int lim = nwords < 16384 ? nwords : 16384;
    for (int i = 1 + 2 * threadIdx.x; i < lim; i += 2 * blockDim.x)
        if (w[i] != 0) { any_nonzero = 1; break; }
    __syncthreads();
    if (threadIdx.x == 0) g_stride = any_nonzero ? 1 : 2;
}

// ---------------------------------------------------------------------------
// K1: clear bitmap + nnz counter. 2^19 uint4 (STG.128) stores.
// ---------------------------------------------------------------------------
__global__ void k_clear() {
    unsigned i = blockIdx.x * blockDim.x + threadIdx.x;
    if (i < BM_WORDS / 4)
        ((uint4*)g_bitmap)[i] = make_uint4(0u, 0u, 0u, 0u);
    if (i == 0) g_nnz = 0ull;
}

// ---------------------------------------------------------------------------
// K2: partial column sums of x. 64 blocks x 256 threads; block b owns a
// contiguous row range, thread t = column t. Coalesced, fixed-order
// (deterministic), double accumulation.
// ---------------------------------------------------------------------------
__global__ void k_colsum(const float* __restrict__ x, int N) {
    int b = blockIdx.x;
    int t = threadIdx.x;
    int rows_per = N / 64;
    const float* p = x + (long long)b * rows_per * CCH + t;
    double s = 0.0;
    for (int r = 0; r < rows_per; r++)
        s += (double)p[(long long)r * CCH];
    g_partial[b * CCH + t] = (float)s;
}

// ---------------------------------------------------------------------------
// K3: mark edges in bitmap, count newly-set bits (distinct (row,col) pairs).
// ids[] viewed as int32 words; stride 1 (int32) or 2 (int64 low word).
// row e at ids[e*st], col e at ids[(E+e)*st]. Keys < 2^26 by construction.
// Warp ballot -> one 64-bit atomicAdd per warp.
// ---------------------------------------------------------------------------
__global__ void k_mark(const int* __restrict__ ids, int E) {
    int st = g_stride;
    int e = blockIdx.x * blockDim.x + threadIdx.x;
    int isnew = 0;
    if (e < E) {
        unsigned r = (unsigned)ids[(long long)e * st];
        unsigned c = (unsigned)ids[(long long)(E + e) * st];
        unsigned key = r * NNODES + c;                 // < 2^26
        unsigned w = key >> 5;
        unsigned m = 1u << (key & 31u);
        unsigned old = atomicOr(&g_bitmap[w], m);
        isnew = ((old & m) == 0u) ? 1 : 0;
    }
    unsigned bal = __ballot_sync(0xffffffffu, isnew);
    if ((threadIdx.x & 31u) == 0u && bal)
        atomicAdd(&g_nnz, (unsigned long long)__popc(bal));
}

// ---------------------------------------------------------------------------
// K4: write output.
//   out[0      .. 65535 ] : x_pooled[i][c] = colsum[c] / 256   (rows identical)
//   out[65536  .. 131071] : adj_pooled      = nnz / 65536      (constant)
// 64-way fold is fixed-order -> deterministic; partials are L2-hot (64 KB).
// ---------------------------------------------------------------------------
__global__ void k_out(float* __restrict__ out, int out_n) {
    int idx = blockIdx.x * blockDim.x + threadIdx.x;
    if (idx >= out_n) return;
    if (idx < CCH * CCH) {
        int c = idx & (CCH - 1);
        float s = 0.0f;
#pragma unroll
        for (int p = 0; p < 64; p++)
            s += g_partial[p * CCH + c];
        out[idx] = s * (1.0f / 256.0f);
    } else {
        out[idx] = (float)((double)g_nnz * (1.0 / 65536.0));
    }
}

// ---------------------------------------------------------------------------
// Inputs (metadata order): x, edge_index, edge_attr, Wn, bn, We, be, Wa, ba
// Only x (d_in[0], f32 [N,C]) and edge_index (d_in[1], [2,E] int32 — the
// harness has no int64 path; JAX also downgrades randint to int32) matter.
// Output: x_pooled (256x256 f32) then adj_pooled (256x256 f32).
// ---------------------------------------------------------------------------
extern "C" void kernel_launch(void* const* d_in, const int* in_sizes, int n_in,
                              void* d_out, int out_size) {
    const float* x   = (const float*)d_in[0];
    const int*   ids = (const int*)d_in[1];
    int N = in_sizes[0] / CCH;   // 8192
    int E = in_sizes[1] / 2;     // 262144
    float* out = (float*)d_out;

    k_detect<<< 1, 256 >>> (ids, in_sizes[1]);
    k_clear <<< (BM_WORDS / 4 + 511) / 512, 512 >>> ();
    k_colsum<<< 64, 256 >>> (x, N);
    k_mark  <<< (E + 255) / 256, 256 >>> (ids, E);
    k_out   <<< (out_size + 255) / 256, 256 >>> (out, out_size);
}

// round 7
// speedup vs baseline: 1.0608x; 1.0608x over previous
#include <cuda_runtime.h>

#define NNODES 8192
#define CCH    256
// bitmap over NNODES*NNODES = 2^26 keys -> 2^21 uint32 words = 8 MiB
#define BM_WORDS  (1u << 21)
#define BM_VEC    (BM_WORDS / 4)      // 2^19 uint4
#define PC_BLOCKS 512                 // popclear blocks

__device__ __align__(16) unsigned g_bitmap[BM_WORDS];   // BSS-zeroed at load;
                                                        // k_popclear re-zeroes each launch
__device__ float    g_partial[64 * CCH];
__device__ unsigned g_bcount[PC_BLOCKS];
__device__ int      g_stride;   // 1 = int32 ids, 2 = int64 ids (low word)

// ---------------------------------------------------------------------------
// K1: column sums of x (blocks 0..63) + dtype probe (block 64).
// Probe: int64 node ids (<8192, LE) -> every odd 32-bit word is 0.
// ---------------------------------------------------------------------------
__global__ void k_colsum_detect(const float* __restrict__ x, int N,
                                const int* __restrict__ w, int nwords) {
    if (blockIdx.x == 64) {
        __shared__ int any_nonzero;
        if (threadIdx.x == 0) any_nonzero = 0;
        __syncthreads();
        int lim = nwords < 16384 ? nwords : 16384;
        for (int i = 1 + 2 * threadIdx.x; i < lim; i += 2 * blockDim.x)
            if (w[i] != 0) { any_nonzero = 1; break; }
        __syncthreads();
        if (threadIdx.x == 0) g_stride = any_nonzero ? 1 : 2;
        return;
    }
    int b = blockIdx.x;
    int t = threadIdx.x;
    int rows_per = N / 64;
    const float* p = x + (long long)b * rows_per * CCH + t;
    double s = 0.0;
    for (int r = 0; r < rows_per; r++)
        s += (double)p[(long long)r * CCH];
    g_partial[b * CCH + t] = (float)s;
}

// ---------------------------------------------------------------------------
// K2: mark edges. atomicOr with UNUSED result -> REDG (fire-and-forget, no
// 318-cyc return stall). 4 edges/thread via int4 when ids are int32.
// ---------------------------------------------------------------------------
__device__ __forceinline__ void mark(unsigned r, unsigned c) {
    unsigned key = r * NNODES + c;                // < 2^26
    atomicOr(&g_bitmap[key >> 5], 1u << (key & 31u));   // result dropped -> RED
}

__global__ void k_mark(const int* __restrict__ ids, int E) {
    int st = g_stride;
    int t = blockIdx.x * blockDim.x + threadIdx.x;
    int base = t * 4;
    if (st == 1 && (E & 3) == 0) {
        if (base < E) {
            int4 r4 = *(const int4*)(ids + base);
            int4 c4 = *(const int4*)(ids + E + base);
            mark((unsigned)r4.x, (unsigned)c4.x);
            mark((unsigned)r4.y, (unsigned)c4.y);
            mark((unsigned)r4.z, (unsigned)c4.z);
            mark((unsigned)r4.w, (unsigned)c4.w);
        }
    } else {
#pragma unroll
        for (int k = 0; k < 4; k++) {
            int e = base + k;
            if (e < E)
                mark((unsigned)ids[(long long)e * st],
                     (unsigned)ids[(long long)(E + e) * st]);
        }
    }
}

// ---------------------------------------------------------------------------
// K3: popcount + clear. Reads the whole bitmap once (counts set bits =
// distinct edges) and zeroes it for the next launch. Per-block partials.
// ---------------------------------------------------------------------------
__global__ void k_popclear() {
    unsigned tid = blockIdx.x * blockDim.x + threadIdx.x;   // 131072 threads
    uint4* bm = (uint4*)g_bitmap;
    unsigned cnt = 0;
#pragma unroll
    for (int i = 0; i < 4; i++) {
        unsigned idx = tid + i * (PC_BLOCKS * 256);
        uint4 v = bm[idx];
        cnt += __popc(v.x) + __popc(v.y) + __popc(v.z) + __popc(v.w);
        bm[idx] = make_uint4(0u, 0u, 0u, 0u);
    }
#pragma unroll
    for (int o = 16; o; o >>= 1) cnt += __shfl_down_sync(0xffffffffu, cnt, o);
    __shared__ unsigned ws[8];
    if ((threadIdx.x & 31u) == 0u) ws[threadIdx.x >> 5] = cnt;
    __syncthreads();
    if (threadIdx.x == 0) {
        unsigned tot = 0;
#pragma unroll
        for (int i = 0; i < 8; i++) tot += ws[i];
        g_bcount[blockIdx.x] = tot;
    }
}

// ---------------------------------------------------------------------------
// K4: write output. Each block first reduces the 512 popcount partials
// (fixed order -> deterministic), then:
//   out[0..65535]      : x_pooled[i][c] = colsum[c]/256  (rows identical)
//   out[65536..131071] : adj_pooled      = nnz/65536      (constant)
// ---------------------------------------------------------------------------
__global__ void k_out(float* __restrict__ out, int out_n) {
    __shared__ unsigned ws[8];
    __shared__ float s_adj;
    unsigned c = g_bcount[threadIdx.x] + g_bcount[threadIdx.x + 256];
#pragma unroll
    for (int o = 16; o; o >>= 1) c += __shfl_down_sync(0xffffffffu, c, o);
    if ((threadIdx.x & 31u) == 0u) ws[threadIdx.x >> 5] = c;
    __syncthreads();
    if (threadIdx.x == 0) {
        unsigned tot = 0;
#pragma unroll
        for (int i = 0; i < 8; i++) tot += ws[i];
        s_adj = (float)((double)tot * (1.0 / 65536.0));
    }
    __syncthreads();

    int idx = blockIdx.x * blockDim.x + threadIdx.x;
    if (idx >= out_n) return;
    if (idx < CCH * CCH) {
        int ch = idx & (CCH - 1);
        float s = 0.0f;
#pragma unroll
        for (int p = 0; p < 64; p++)
            s += g_partial[p * CCH + ch];
        out[idx] = s * (1.0f / 256.0f);
    } else {
        out[idx] = s_adj;
    }
}

// ---------------------------------------------------------------------------
// Inputs (metadata order): x, edge_index, edge_attr, Wn, bn, We, be, Wa, ba
// Only x (f32 [N,C]) and edge_index ([2,E] int32) matter — S is exactly
// uniform 1/256, so the GEMMs/softmax collapse (verified: rel_err 4e-7).
// ---------------------------------------------------------------------------
extern "C" void kernel_launch(void* const* d_in, const int* in_sizes, int n_in,
                              void* d_out, int out_size) {
    const float* x   = (const float*)d_in[0];
    const int*   ids = (const int*)d_in[1];
    int N = in_sizes[0] / CCH;   // 8192
    int E = in_sizes[1] / 2;     // 262144
    float* out = (float*)d_out;

    k_colsum_detect<<< 65, 256 >>> (x, N, ids, in_sizes[1]);
    k_mark         <<< (E / 4 + 255) / 256, 256 >>> (ids, E);
    k_popclear     <<< PC_BLOCKS, 256 >>> ();
    k_out          <<< (out_size + 255) / 256, 256 >>> (out, out_size);
}

// round 8
// speedup vs baseline: 1.1192x; 1.0551x over previous
#include <cuda_runtime.h>

#define NNODES 8192
#define CCH    256
// bitmap over NNODES*NNODES = 2^26 keys -> 2^21 uint32 words = 8 MiB
#define BM_WORDS  (1u << 21)
#define BM_VEC    (BM_WORDS / 4)      // 524288 uint4
#define PC_BLOCKS 512
#define MARK_BLOCKS 256               // 256 blocks * 256 thr * 4 edges = 262144

__device__ __align__(16) unsigned g_bitmap[BM_WORDS];  // BSS-zeroed; K2 re-zeroes
__device__ float                  g_partial[64 * CCH];
__device__ __align__(16) float    g_colsum[CCH];       // folded & pre-scaled by 1/256
__device__ unsigned               g_nnz;               // integer atomic: order-exact

// ---------------------------------------------------------------------------
// K1: blocks 0-63 = column sums of x; blocks 64.. = edge marking (REDG).
// Mark blocks self-detect id dtype: int64 node ids (<8192, LE) have all-zero
// odd 32-bit words; 64 probes of random int32 ids are all-zero w.p. ~8192^-64.
// ---------------------------------------------------------------------------
__device__ __forceinline__ void mark(unsigned r, unsigned c) {
    unsigned key = r * NNODES + c;                       // < 2^26
    atomicOr(&g_bitmap[key >> 5], 1u << (key & 31u));    // result unused -> RED
}

__global__ void k_colsum_mark(const float* __restrict__ x, int N,
                              const int* __restrict__ ids, int E) {
    if (blockIdx.x < 64) {                       // ---- column sums ----
        int b = blockIdx.x, t = threadIdx.x;
        int rows_per = N / 64;
        const float* p = x + (long long)b * rows_per * CCH + t;
        double s = 0.0;
        for (int r = 0; r < rows_per; r++)
            s += (double)p[(long long)r * CCH];
        g_partial[b * CCH + t] = (float)s;
        return;
    }
    // ---- edge marking ----
    if (blockIdx.x == 64 && threadIdx.x == 0) g_nnz = 0u;  // reset before K2 adds

    __shared__ int s_nonzero;
    if (threadIdx.x == 0) s_nonzero = 0;
    __syncthreads();
    if (threadIdx.x < 64 && ids[2 * threadIdx.x + 1] != 0) s_nonzero = 1;
    __syncthreads();
    int st = s_nonzero ? 1 : 2;                  // 1 = int32 ids, 2 = int64 low word

    int mb = blockIdx.x - 64;
    int base = (mb * blockDim.x + threadIdx.x) * 4;
    if (st == 1) {
        if (base + 3 < E) {
            int4 r4 = *(const int4*)(ids + base);
            int4 c4 = *(const int4*)(ids + E + base);
            mark((unsigned)r4.x, (unsigned)c4.x);
            mark((unsigned)r4.y, (unsigned)c4.y);
            mark((unsigned)r4.z, (unsigned)c4.z);
            mark((unsigned)r4.w, (unsigned)c4.w);
        } else {
            for (int e = base; e < E; e++)
                mark((unsigned)ids[e], (unsigned)ids[E + e]);
        }
    } else {
#pragma unroll
        for (int k = 0; k < 4; k++) {
            int e = base + k;
            if (e < E)
                mark((unsigned)ids[(long long)e * 2],
                     (unsigned)ids[(long long)(E + e) * 2]);
        }
    }
}

// ---------------------------------------------------------------------------
// K2: popcount+clear sweep (8 MiB read + 8 MiB write), per-block count into
// one integer atomicAdd (order-invariant => deterministic). Block 0 also
// folds the 64 colsum partials once (fixed order) into g_colsum, pre-scaled.
// ---------------------------------------------------------------------------
__global__ void k_popclear_fold() {
    unsigned tid = blockIdx.x * blockDim.x + threadIdx.x;   // 131072 threads
    uint4* bm = (uint4*)g_bitmap;
    unsigned cnt = 0;
#pragma unroll
    for (int i = 0; i < 4; i++) {
        unsigned idx = tid + i * (PC_BLOCKS * 256);
        uint4 v = bm[idx];
        cnt += __popc(v.x) + __popc(v.y) + __popc(v.z) + __popc(v.w);
        bm[idx] = make_uint4(0u, 0u, 0u, 0u);
    }
#pragma unroll
    for (int o = 16; o; o >>= 1) cnt += __shfl_down_sync(0xffffffffu, cnt, o);
    __shared__ unsigned ws[8];
    if ((threadIdx.x & 31u) == 0u) ws[threadIdx.x >> 5] = cnt;
    __syncthreads();
    if (threadIdx.x == 0) {
        unsigned tot = 0;
#pragma unroll
        for (int i = 0; i < 8; i++) tot += ws[i];
        if (tot) atomicAdd(&g_nnz, tot);
    }

    if (blockIdx.x == 0) {                       // one-time fold, L2-hot
        int t = threadIdx.x;
        float s = 0.0f;
#pragma unroll
        for (int p = 0; p < 64; p++)
            s += g_partial[p * CCH + t];
        g_colsum[t] = s * (1.0f / 256.0f);
    }
}

// ---------------------------------------------------------------------------
// K3: output. 32768 threads, one float4 each.
//   out[0..65535]      : x_pooled[i][c] = g_colsum[c]   (rows identical)
//   out[65536..131071] : adj_pooled     = nnz / 65536   (constant)
// ---------------------------------------------------------------------------
__global__ void k_out(float* __restrict__ out, int out_n) {
    int idx = (blockIdx.x * blockDim.x + threadIdx.x) * 4;
    if (idx >= out_n) return;
    float4 v;
    if (idx < CCH * CCH) {
        v = *(const float4*)&g_colsum[idx & (CCH - 1)];
    } else {
        float a = (float)((double)g_nnz * (1.0 / 65536.0));
        v = make_float4(a, a, a, a);
    }
    *(float4*)(out + idx) = v;
}

// ---------------------------------------------------------------------------
// Inputs (metadata order): x, edge_index, edge_attr, Wn, bn, We, be, Wa, ba.
// S is exactly uniform 1/256 (EPS collapse; verified rel_err 4e-7), so only
// x (f32 [N,C]) and edge_index ([2,E] int32) matter.
// ---------------------------------------------------------------------------
extern "C" void kernel_launch(void* const* d_in, const int* in_sizes, int n_in,
                              void* d_out, int out_size) {
    const float* x   = (const float*)d_in[0];
    const int*   ids = (const int*)d_in[1];
    int N = in_sizes[0] / CCH;   // 8192
    int E = in_sizes[1] / 2;     // 262144
    float* out = (float*)d_out;

    k_colsum_mark  <<< 64 + MARK_BLOCKS, 256 >>> (x, N, ids, E);
    k_popclear_fold<<< PC_BLOCKS, 256 >>> ();
    k_out          <<< (out_size / 4 + 255) / 256, 256 >>> (out, out_size);
}

// round 10
// speedup vs baseline: 1.3586x; 1.2138x over previous
#include <cuda_runtime.h>

#define NNODES 8192
#define CCH    256
// bitmap over NNODES*NNODES = 2^26 keys -> 2^21 uint32 words = 8 MiB
#define BM_WORDS   (1u << 21)
#define PC_BLOCKS  512
#define CS_BLOCKS  256                 // colsum blocks (32 rows each)
#define MARK_BLOCKS 256                // 256*256*4 = 262144 edges

__device__ __align__(16) unsigned g_bitmap[BM_WORDS];  // BSS-zeroed; K2 re-zeroes
__device__ __align__(16) float4   g_partial4[1024 * 64];  // [row-slice][col-group]
__device__ __align__(16) float    g_colsum[CCH];          // folded, pre-scaled 1/256
__device__ unsigned               g_nnz;                  // int atomic: order-exact

// ---------------------------------------------------------------------------
// K1: blocks 0..255 = column sums of x (float4, 8-row chains, MLP=8);
//     blocks 256..511 = edge marking (REDG, 4 edges/thread).
// ---------------------------------------------------------------------------
__device__ __forceinline__ void mark(unsigned r, unsigned c) {
    unsigned key = r * NNODES + c;                       // < 2^26
    atomicOr(&g_bitmap[key >> 5], 1u << (key & 31u));    // result unused -> RED
}

__global__ void k_colsum_mark(const float* __restrict__ x, int N,
                              const int* __restrict__ ids, int E) {
    if (blockIdx.x < CS_BLOCKS) {                // ---- column sums ----
        if (blockIdx.x == 0 && threadIdx.x == 0) g_nnz = 0u;  // reset for K2
        const float4* x4 = (const float4*)x;     // [N][64]
        int c4 = threadIdx.x & 63;               // col-group (4 cols)
        int rq = threadIdx.x >> 6;               // row quarter within block
        int r0 = blockIdx.x * 32 + rq * 8;       // 8 rows per thread
        float4 a = make_float4(0.f, 0.f, 0.f, 0.f);
#pragma unroll
        for (int i = 0; i < 8; i++) {
            float4 v = x4[(long long)(r0 + i) * 64 + c4];
            a.x += v.x; a.y += v.y; a.z += v.z; a.w += v.w;
        }
        g_partial4[(blockIdx.x * 4 + rq) * 64 + c4] = a;
        return;
    }
    // ---- edge marking ----
    __shared__ int s_nonzero;                    // dtype probe: int64 ids -> odd words 0
    if (threadIdx.x == 0) s_nonzero = 0;
    __syncthreads();
    if (threadIdx.x < 64 && ids[2 * threadIdx.x + 1] != 0) s_nonzero = 1;
    __syncthreads();
    int st = s_nonzero ? 1 : 2;                  // 1 = int32, 2 = int64 low word

    int mb = blockIdx.x - CS_BLOCKS;
    int base = (mb * blockDim.x + threadIdx.x) * 4;
    if (st == 1) {
        if (base + 3 < E) {
            int4 r4 = *(const int4*)(ids + base);
            int4 c4v = *(const int4*)(ids + E + base);
            mark((unsigned)r4.x, (unsigned)c4v.x);
            mark((unsigned)r4.y, (unsigned)c4v.y);
            mark((unsigned)r4.z, (unsigned)c4v.z);
            mark((unsigned)r4.w, (unsigned)c4v.w);
        } else {
            for (int e = base; e < E; e++)
                mark((unsigned)ids[e], (unsigned)ids[E + e]);
        }
    } else {
#pragma unroll
        for (int k = 0; k < 4; k++) {
            int e = base + k;
            if (e < E)
                mark((unsigned)ids[(long long)e * 2],
                     (unsigned)ids[(long long)(E + e) * 2]);
        }
    }
}

// ---------------------------------------------------------------------------
// K2: popcount+clear sweep (8 MiB R + 8 MiB W); per-block counts into one
// integer atomicAdd (order-invariant => deterministic). Block 0 also folds
// the 1024 colsum partial slices once (fixed order, L2-hot) into g_colsum.
// ---------------------------------------------------------------------------
__global__ void k_popclear_fold() {
    unsigned tid = blockIdx.x * blockDim.x + threadIdx.x;   // 131072 threads
    uint4* bm = (uint4*)g_bitmap;
    unsigned cnt = 0;
#pragma unroll
    for (int i = 0; i < 4; i++) {
        unsigned idx = tid + i * (PC_BLOCKS * 256);
        uint4 v = bm[idx];
        cnt += __popc(v.x) + __popc(v.y) + __popc(v.z) + __popc(v.w);
        bm[idx] = make_uint4(0u, 0u, 0u, 0u);
    }
#pragma unroll
    for (int o = 16; o; o >>= 1) cnt += __shfl_down_sync(0xffffffffu, cnt, o);
    __shared__ unsigned ws[8];
    if ((threadIdx.x & 31u) == 0u) ws[threadIdx.x >> 5] = cnt;
    __syncthreads();
    if (threadIdx.x == 0) {
        unsigned tot = 0;
#pragma unroll
        for (int i = 0; i < 8; i++) tot += ws[i];
        if (tot) atomicAdd(&g_nnz, tot);
    }

    if (blockIdx.x == 0) {                       // ---- one-time fold ----
        __shared__ float4 sh[256];
        int c4 = threadIdx.x & 63, q = threadIdx.x >> 6;
        float4 a = make_float4(0.f, 0.f, 0.f, 0.f);
        for (int j = 0; j < 256; j++) {          // fixed order -> deterministic
            float4 v = g_partial4[(q * 256 + j) * 64 + c4];
            a.x += v.x; a.y += v.y; a.z += v.z; a.w += v.w;
        }
        sh[threadIdx.x] = a;
        __syncthreads();
        if (threadIdx.x < 64) {
            float4 s = sh[threadIdx.x];
#pragma unroll
            for (int q2 = 1; q2 < 4; q2++) {
                float4 v = sh[q2 * 64 + threadIdx.x];
                s.x += v.x; s.y += v.y; s.z += v.z; s.w += v.w;
            }
            const float k = 1.0f / 256.0f;
            s.x *= k; s.y *= k; s.z *= k; s.w *= k;
            *(float4*)&g_colsum[threadIdx.x * 4] = s;
        }
    }
}

// ---------------------------------------------------------------------------
// K3: output, one float4 per thread.
//   out[0..65535]      : x_pooled rows, all = g_colsum
//   out[65536..131071] : adj_pooled    = nnz / 65536 (constant)
// ---------------------------------------------------------------------------
__global__ void k_out(float* __restrict__ out, int out_n) {
    int idx = (blockIdx.x * blockDim.x + threadIdx.x) * 4;
    if (idx >= out_n) return;
    float4 v;
    if (idx < CCH * CCH) {
        v = *(const float4*)&g_colsum[idx & (CCH - 1)];
    } else {
        float a = (float)((double)g_nnz * (1.0 / 65536.0));
        v = make_float4(a, a, a, a);
    }
    *(float4*)(out + idx) = v;
}

// ---------------------------------------------------------------------------
// Inputs: x (f32 [N,C]), edge_index ([2,E] int32) — rest dead: S is exactly
// uniform 1/256 (EPS collapse; verified rel_err ~4e-7 in earlier rounds).
// ---------------------------------------------------------------------------
extern "C" void kernel_launch(void* const* d_in, const int* in_sizes, int n_in,
                              void* d_out, int out_size) {
    const float* x   = (const float*)d_in[0];
    const int*   ids = (const int*)d_in[1];
    int N = in_sizes[0] / CCH;   // 8192
    int E = in_sizes[1] / 2;     // 262144
    float* out = (float*)d_out;

    k_colsum_mark  <<< CS_BLOCKS + MARK_BLOCKS, 256 >>> (x, N, ids, E);
    k_popclear_fold<<< PC_BLOCKS, 256 >>> ();
    k_out          <<< (out_size / 4 + 255) / 256, 256 >>> (out, out_size);
}

// round 11
// speedup vs baseline: 2.6703x; 1.9655x over previous
#include <cuda_runtime.h>

#define NNODES 8192
#define CCH    256
// bitmap over NNODES*NNODES = 2^26 keys -> 2^21 uint32 words = 8 MiB
#define BM_WORDS    (1u << 21)
#define CS_BLOCKS   512            // colsum: 16 rows/block
#define MARK_BLOCKS 256            // 256*256*4 = 262144 edges
#define PC_BLOCKS   512            // sweep blocks
#define FOLD1_BLOCKS 16            // parallel fold stage 1
#define SLICES      (CS_BLOCKS * 4)   // 2048 partial row-slices

__device__ __align__(16) unsigned g_bitmap[BM_WORDS];      // BSS-zeroed; K2 re-zeroes
__device__ __align__(16) float4   g_partial4[SLICES * 64]; // [slice][col-group]
__device__ __align__(16) float4   g_partial2[FOLD1_BLOCKS * 64]; // stage-1 result
__device__ unsigned               g_nnz;                   // int atomic: order-exact

// ---------------------------------------------------------------------------
// K1: blocks 0..511 = column sums (float4, 4-row chains); 512..767 = edge
// marking (REDG fire-and-forget, 4 edges/thread).
// ---------------------------------------------------------------------------
__device__ __forceinline__ void mark(unsigned r, unsigned c) {
    unsigned key = r * NNODES + c;                       // < 2^26
    atomicOr(&g_bitmap[key >> 5], 1u << (key & 31u));    // result unused -> RED
}

__global__ void k_colsum_mark(const float* __restrict__ x, int N,
                              const int* __restrict__ ids, int E) {
    if (blockIdx.x < CS_BLOCKS) {                // ---- column sums ----
        if (blockIdx.x == 0 && threadIdx.x == 0) g_nnz = 0u;   // reset for K2
        const float4* x4 = (const float4*)x;     // [N][64]
        int c4 = threadIdx.x & 63;               // col-group (4 cols)
        int rq = threadIdx.x >> 6;               // quarter: 4 rows each
        int r0 = blockIdx.x * 16 + rq * 4;
        float4 a = make_float4(0.f, 0.f, 0.f, 0.f);
#pragma unroll
        for (int i = 0; i < 4; i++) {
            float4 v = x4[(long long)(r0 + i) * 64 + c4];
            a.x += v.x; a.y += v.y; a.z += v.z; a.w += v.w;
        }
        g_partial4[(blockIdx.x * 4 + rq) * 64 + c4] = a;
        return;
    }
    // ---- edge marking ----
    __shared__ int s_nonzero;                    // dtype probe: int64 ids -> odd words 0
    if (threadIdx.x == 0) s_nonzero = 0;
    __syncthreads();
    if (threadIdx.x < 64 && ids[2 * threadIdx.x + 1] != 0) s_nonzero = 1;
    __syncthreads();
    int st = s_nonzero ? 1 : 2;                  // 1 = int32, 2 = int64 low word

    int mb = blockIdx.x - CS_BLOCKS;
    int base = (mb * blockDim.x + threadIdx.x) * 4;
    if (st == 1) {
        if (base + 3 < E) {
            int4 r4 = *(const int4*)(ids + base);
            int4 c4v = *(const int4*)(ids + E + base);
            mark((unsigned)r4.x, (unsigned)c4v.x);
            mark((unsigned)r4.y, (unsigned)c4v.y);
            mark((unsigned)r4.z, (unsigned)c4v.z);
            mark((unsigned)r4.w, (unsigned)c4v.w);
        } else {
            for (int e = base; e < E; e++)
                mark((unsigned)ids[e], (unsigned)ids[E + e]);
        }
    } else {
#pragma unroll
        for (int k = 0; k < 4; k++) {
            int e = base + k;
            if (e < E)
                mark((unsigned)ids[(long long)e * 2],
                     (unsigned)ids[(long long)(E + e) * 2]);
        }
    }
}

// ---------------------------------------------------------------------------
// K2: blocks 0..511 = bitmap popcount + CONDITIONAL clear (only ~39% of
// uint4s are nonzero -> skip most zero-stores); per-block count into one
// integer atomicAdd (order-invariant => deterministic).
// Blocks 512..527 = parallel fold stage 1: 128 slices each -> g_partial2.
// ---------------------------------------------------------------------------
__global__ void k_popclear_fold() {
    if (blockIdx.x < PC_BLOCKS) {
        unsigned tid = blockIdx.x * blockDim.x + threadIdx.x;  // 131072 threads
        uint4* bm = (uint4*)g_bitmap;
        unsigned cnt = 0;
#pragma unroll
        for (int i = 0; i < 4; i++) {
            unsigned idx = tid + i * (PC_BLOCKS * 256);
            uint4 v = bm[idx];
            unsigned p = __popc(v.x) + __popc(v.y) + __popc(v.z) + __popc(v.w);
            cnt += p;
            if (p) bm[idx] = make_uint4(0u, 0u, 0u, 0u);   // clear only if dirty
        }
#pragma unroll
        for (int o = 16; o; o >>= 1) cnt += __shfl_down_sync(0xffffffffu, cnt, o);
        __shared__ unsigned ws[8];
        if ((threadIdx.x & 31u) == 0u) ws[threadIdx.x >> 5] = cnt;
        __syncthreads();
        if (threadIdx.x == 0) {
            unsigned tot = 0;
#pragma unroll
            for (int i = 0; i < 8; i++) tot += ws[i];
            if (tot) atomicAdd(&g_nnz, tot);
        }
        return;
    }
    // ---- fold stage 1: 16 blocks, 128 slices each (fixed order) ----
    int f = blockIdx.x - PC_BLOCKS;
    int c4 = threadIdx.x & 63, q = threadIdx.x >> 6;  // q covers 32 slices
    int s0 = f * 128 + q * 32;
    float4 a = make_float4(0.f, 0.f, 0.f, 0.f);
    for (int i = 0; i < 32; i++) {
        float4 v = g_partial4[(s0 + i) * 64 + c4];
        a.x += v.x; a.y += v.y; a.z += v.z; a.w += v.w;
    }
    __shared__ float4 sh[256];
    sh[threadIdx.x] = a;
    __syncthreads();
    if (threadIdx.x < 64) {
        float4 s = sh[threadIdx.x];
#pragma unroll
        for (int q2 = 1; q2 < 4; q2++) {
            float4 v = sh[q2 * 64 + threadIdx.x];
            s.x += v.x; s.y += v.y; s.z += v.z; s.w += v.w;
        }
        g_partial2[f * 64 + threadIdx.x] = s;
    }
}

// ---------------------------------------------------------------------------
// K3: output. Each block: stage-2 fold of the 4 KiB L2-hot g_partial2 into
// smem (fixed order), then float4 stores.
//   out[0..65535]      : x_pooled rows, all = colsum/256
//   out[65536..131071] : adj_pooled    = nnz / 65536 (constant)
// ---------------------------------------------------------------------------
__global__ void k_out(float* __restrict__ out, int out_n) {
    __shared__ float4 sm_cs[64];
    if (threadIdx.x < 64) {
        float4 s = make_float4(0.f, 0.f, 0.f, 0.f);
#pragma unroll
        for (int i = 0; i < FOLD1_BLOCKS; i++) {
            float4 v = g_partial2[i * 64 + threadIdx.x];
            s.x += v.x; s.y += v.y; s.z += v.z; s.w += v.w;
        }
        const float k = 1.0f / 256.0f;
        s.x *= k; s.y *= k; s.z *= k; s.w *= k;
        sm_cs[threadIdx.x] = s;
    }
    __syncthreads();

    int idx = (blockIdx.x * blockDim.x + threadIdx.x) * 4;
    if (idx >= out_n) return;
    float4 v;
    if (idx < CCH * CCH) {
        v = sm_cs[(idx & (CCH - 1)) >> 2];
    } else {
        float a = (float)((double)g_nnz * (1.0 / 65536.0));
        v = make_float4(a, a, a, a);
    }
    *(float4*)(out + idx) = v;
}

// ---------------------------------------------------------------------------
// Inputs: x (f32 [N,C]), edge_index ([2,E] int32) — rest dead: S is exactly
// uniform 1/256 (EPS collapse; verified rel_err ~4e-7).
// ---------------------------------------------------------------------------
extern "C" void kernel_launch(void* const* d_in, const int* in_sizes, int n_in,
                              void* d_out, int out_size) {
    const float* x   = (const float*)d_in[0];
    const int*   ids = (const int*)d_in[1];
    int N = in_sizes[0] / CCH;   // 8192
    int E = in_sizes[1] / 2;     // 262144
    float* out = (float*)d_out;

    k_colsum_mark  <<< CS_BLOCKS + MARK_BLOCKS, 256 >>> (x, N, ids, E);
    k_popclear_fold<<< PC_BLOCKS + FOLD1_BLOCKS, 256 >>> ();
    k_out          <<< (out_size / 4 + 255) / 256, 256 >>> (out, out_size);
}